// round 15
// baseline (speedup 1.0000x reference)
#include <cuda_runtime.h>
#include <cuda_fp16.h>
#include <math.h>
#include <stdint.h>

// Problem dims
#define NPIX (16*64*64)      // 65536 pixels
#define DIMC 512
#define AK   576             // padded K: 512 (c) + 32 (mixed) + 32 (zeros)

// -------- scratch (device globals; no allocations allowed) --------
__device__ __align__(16) float g_t[NPIX*32];        // proj_in outputs
__device__ __align__(16) float g_mixed[NPIX*32];    // windowed-mixing outputs (fp32)
__device__ __align__(16) float g_part[1024*DIMC];   // partial sums of c (spatial mean)
__device__ __align__(16) float g_mmean2[16*8*32];   // per-(batch,slab) sums of mixed
__device__ __align__(16) float g_a3[3*16*DIMC];     // softmax reweight coefficients
__device__ __align__(16) float g_bias[16*DIMC];     // per-batch fused bias vector
__device__ __align__(16) float g_WtT[DIMC*DIMC];    // proj_w^T fp32 [n][k]
// fp16 operands for the final GEMM (K padded to 576)
__device__ __align__(16) __half g_Ahi[NPIX*AK];       // A plane [m][576]
__device__ __align__(16) __half g_Bmat[16*DIMC*AK];   // per-batch B^T [b][n][576]

// ---------------- PTX helpers (portable sm_80+ subset) ----------------
__device__ __forceinline__ uint32_t smem_u32(const void* p) {
    uint32_t a;
    asm("{ .reg .u64 t; cvta.to.shared.u64 t, %1; cvt.u32.u64 %0, t; }" : "=r"(a) : "l"(p));
    return a;
}
#define CP_ASYNC16(dst, src) \
    asm volatile("cp.async.cg.shared.global [%0], [%1], 16;" :: "r"(dst), "l"(src))
#define CP_COMMIT() asm volatile("cp.async.commit_group;" ::: "memory")
#define CP_WAIT1()  asm volatile("cp.async.wait_group 1;" ::: "memory")
#define CP_WAIT0()  asm volatile("cp.async.wait_group 0;" ::: "memory")

#define LDMATRIX_X4(r0, r1, r2, r3, addr) \
    asm volatile("ldmatrix.sync.aligned.m8n8.x4.shared.b16 {%0,%1,%2,%3}, [%4];" \
                 : "=r"(r0), "=r"(r1), "=r"(r2), "=r"(r3) : "r"(addr))

#define MMA_FP16(c0, c1, c2, c3, a0, a1, a2, a3, b0, b1) \
    asm volatile("mma.sync.aligned.m16n8k16.row.col.f32.f16.f16.f32 " \
                 "{%0,%1,%2,%3}, {%4,%5,%6,%7}, {%8,%9}, {%0,%1,%2,%3};" \
                 : "+f"(c0), "+f"(c1), "+f"(c2), "+f"(c3) \
                 : "r"(a0), "r"(a1), "r"(a2), "r"(a3), "r"(b0), "r"(b1))

// packed fp32x2 FMA (kept in K1 only)
#define FMA_F32X2(d, a, b, c) \
    asm("fma.rn.f32x2 %0, %1, %2, %3;" : "=l"(d) : "l"(a), "l"(b), "l"(c))
#define PACK2(d, f) \
    asm("mov.b64 %0, {%1, %1};" : "=l"(d) : "f"(f))
#define UNPACK2(lo, hi, v) \
    asm("mov.b64 {%0, %1}, %2;" : "=f"(lo), "=f"(hi) : "l"(v))

// ====================================================================
// K5w1: fp32 transpose of proj_w -> g_WtT[n][k]. Tiled via smem.
// ====================================================================
__global__ __launch_bounds__(256) void k5w1_transpose(const float* __restrict__ pw)
{
    __shared__ float ts[32][33];
    const int k0 = blockIdx.x * 32;
    const int n0 = blockIdx.y * 32;
    const int t = threadIdx.x;
    const int tr = t >> 5, tc = t & 31;
    #pragma unroll
    for (int rep = 0; rep < 4; rep++) {
        int row = tr + rep * 8;
        ts[row][tc] = pw[(size_t)(k0 + row) * 512 + n0 + tc];
    }
    __syncthreads();
    #pragma unroll
    for (int rep = 0; rep < 4; rep++) {
        int row = tr + rep * 8;
        g_WtT[(size_t)(n0 + row) * 512 + k0 + tc] = ts[tc][row];
    }
}

// ====================================================================
// K1: fused proj_in for both branches.  GEMM M=65536, N=32, K=512.
// ====================================================================
__global__ __launch_bounds__(256) void k1_proj_in(
    const float* __restrict__ x,
    const float* __restrict__ w0, const float* __restrict__ b0,
    const float* __restrict__ w1, const float* __restrict__ b1)
{
    __shared__ float Xs[64][132];
    __shared__ float Ws[64][32];
    const int t = threadIdx.x;
    const int pbase = blockIdx.x * 128;
    const int p    = t >> 1;
    const int koff = (t & 1) * 32;
    const int tr = t >> 3;
    const int tc = t & 7;

    unsigned long long accp[4][2];
    #pragma unroll
    for (int r = 0; r < 4; r++) { accp[r][0] = 0ull; accp[r][1] = 0ull; }

    for (int kc = 0; kc < 512; kc += 64) {
        __syncthreads();
        #pragma unroll
        for (int i = 0; i < 8; i++) {
            float4 v = *(const float4*)(x + (size_t)(pbase + p) * 512 + kc + koff + i * 4);
            Xs[koff + i*4 + 0][p] = v.x;
            Xs[koff + i*4 + 1][p] = v.y;
            Xs[koff + i*4 + 2][p] = v.z;
            Xs[koff + i*4 + 3][p] = v.w;
        }
        #pragma unroll
        for (int i = 0; i < 8; i++) {
            int idx = t + i * 256;
            int k = idx >> 5, j = idx & 31;
            Ws[k][j] = (j < 16) ? w0[(kc + k) * 16 + j] : w1[(kc + k) * 16 + (j - 16)];
        }
        __syncthreads();
        #pragma unroll
        for (int kk = 0; kk < 64; kk++) {
            float4 av = *(const float4*)&Xs[kk][tr * 4];
            const unsigned long long* bp = (const unsigned long long*)&Ws[kk][tc * 4];
            unsigned long long b20 = bp[0], b21 = bp[1];
            unsigned long long aa;
            PACK2(aa, av.x); FMA_F32X2(accp[0][0], aa, b20, accp[0][0]); FMA_F32X2(accp[0][1], aa, b21, accp[0][1]);
            PACK2(aa, av.y); FMA_F32X2(accp[1][0], aa, b20, accp[1][0]); FMA_F32X2(accp[1][1], aa, b21, accp[1][1]);
            PACK2(aa, av.z); FMA_F32X2(accp[2][0], aa, b20, accp[2][0]); FMA_F32X2(accp[2][1], aa, b21, accp[2][1]);
            PACK2(aa, av.w); FMA_F32X2(accp[3][0], aa, b20, accp[3][0]); FMA_F32X2(accp[3][1], aa, b21, accp[3][1]);
        }
    }
    float bb[4];
    #pragma unroll
    for (int j = 0; j < 4; j++) { int c = tc*4 + j; bb[j] = (c < 16) ? b0[c] : b1[c - 16]; }

    #pragma unroll
    for (int r = 0; r < 4; r++) {
        float v0, v1, v2, v3;
        UNPACK2(v0, v1, accp[r][0]);
        UNPACK2(v2, v3, accp[r][1]);
        float4 o = make_float4(v0+bb[0], v1+bb[1], v2+bb[2], v3+bb[3]);
        *(float4*)(g_t + (size_t)(pbase + tr*4 + r) * 32 + tc*4) = o;
    }
}

// ====================================================================
// K2: windowed mixing, 256 threads = 2 window-groups sharing the
// cached weight matrix. 8 windows/pass, 8 passes. (was 128 thr, 16 pass)
// ====================================================================
__global__ __launch_bounds__(256) void k2_mix(
    const float* __restrict__ fw0, const float* __restrict__ fb0,
    const float* __restrict__ fw1, const float* __restrict__ fb1)
{
    extern __shared__ float sm[];
    float (*Wsm)[129] = (float (*)[129])sm;
    __shared__ float vst[2][128][4];

    const int mix  = blockIdx.x >> 7;
    const int head = (blockIdx.x >> 4) & 7;
    const int wt   = blockIdx.x & 15;
    const float* fw = mix ? fw1 : fw0;
    const float* fb = mix ? fb1 : fb0;
    const int tt = threadIdx.x;
    const int t   = tt & 127;      // f-index / d-index lane
    const int grp = tt >> 7;       // window group 0/1

    for (int i = tt; i < 128 * 128; i += 256) {
        int d = i & 127;
        int f = i >> 7;
        Wsm[d][f] = fw[f * 1024 + head * 128 + d];
    }
    const int ch = mix * 16 + head * 2 + (t & 1);
    const float fbv = fb[t];
    __syncthreads();

    for (int pass = 0; pass < 8; pass++) {
        int px[4];
        #pragma unroll
        for (int j = 0; j < 4; j++) {
            int wg = wt * 64 + pass * 8 + grp * 4 + j;
            int Bb = wg >> 4, nw = wg & 15;
            int b = Bb >> 2, n1 = (Bb >> 1) & 1, n2 = Bb & 1;
            int row, col;
            if (mix == 0) { row = 2 * (t >> 2) + n1;          col = 4 * nw + 2 * ((t >> 1) & 1) + n2; }
            else          { row = 4 * nw + 2 * (t >> 6) + n1; col = 2 * ((t >> 1) & 31) + n2; }
            int pix = (b * 64 + row) * 64 + col;
            px[j] = pix;
            vst[grp][t][j] = g_t[(size_t)pix * 32 + ch];
        }
        __syncthreads();
        float a0 = fbv, a1 = fbv, a2 = fbv, a3 = fbv;
        #pragma unroll 8
        for (int d = 0; d < 128; d++) {
            float4 vv = *(const float4*)&vst[grp][d][0];
            float wv = Wsm[d][t];
            a0 += vv.x * wv; a1 += vv.y * wv; a2 += vv.z * wv; a3 += vv.w * wv;
        }
        g_mixed[(size_t)px[0] * 32 + ch] = a0;
        g_mixed[(size_t)px[1] * 32 + ch] = a1;
        g_mixed[(size_t)px[2] * 32 + ch] = a2;
        g_mixed[(size_t)px[3] * 32 + ch] = a3;
        __syncthreads();
    }
}

// ====================================================================
// K3: MixC only -> fp16 A plane (cols 0..511) + partial sums of c.
// Launched as two half-grids (off = 0, 1024) so k1 lands in ncu slot 4.
// ====================================================================
__global__ __launch_bounds__(256) void k3_mixc(
    const float* __restrict__ x,
    const float* __restrict__ cwg, const float* __restrict__ cbg,
    int off)
{
    const int bx = blockIdx.x + off;      // 2048 = 16 b * 64 tile * 2 chHalf
    const int b = bx >> 7;
    const int rem = bx & 127;
    const int tile = rem >> 1;
    const int chH = rem & 1;
    const int ty = tile >> 3, tx = tile & 7;
    const int ch = chH * 256 + threadIdx.x;

    float cwr[16], cbr[4];
    #pragma unroll
    for (int i = 0; i < 16; i++) cwr[i] = cwg[ch*16 + i];
    #pragma unroll
    for (int p = 0; p < 4; p++) cbr[p] = cbg[ch*4 + p];

    float ssum = 0.f;
    #pragma unroll 2
    for (int bi = 0; bi < 16; bi++) {
        int brow = bi >> 2, bcol = bi & 3;
        int r0 = ty*8 + brow*2, c0 = tx*8 + bcol*2;
        float x4[4];
        #pragma unroll
        for (int q = 0; q < 4; q++) {
            int q1 = q >> 1, q2 = q & 1;
            x4[q] = x[(size_t)((b*64 + r0 + q1) * 64 + c0 + q2) * 512 + ch];
        }
        #pragma unroll
        for (int p = 0; p < 4; p++) {
            int p1 = p >> 1, p2 = p & 1;
            float cv = cbr[p];
            #pragma unroll
            for (int q = 0; q < 4; q++) cv += x4[q] * cwr[q*4 + p];
            const size_t pix = (size_t)((b*64 + r0 + p1) * 64 + c0 + p2);
            g_Ahi[pix * AK + ch] = __float2half_rn(cv);
            ssum += cv;
        }
    }
    g_part[(size_t)(b*64 + tile) * 512 + ch] = ssum;
}

// ====================================================================
// K2m: per-(batch, 512-pixel slab) sums of g_mixed -> g_mmean2.
// ====================================================================
__global__ __launch_bounds__(256) void k2m_mean()
{
    __shared__ float red[8][32];
    const int b = blockIdx.x, gg = blockIdx.y;
    const int t = threadIdx.x;
    const int cc = t & 31, sub = t >> 5;
    float s = 0.f;
    const float* src = g_mixed + ((size_t)(b * 4096 + gg * 512 + sub * 64)) * 32 + cc;
    #pragma unroll 8
    for (int i = 0; i < 64; i++) s += src[(size_t)i * 32];
    red[sub][cc] = s;
    __syncthreads();
    if (t < 32) {
        float tot = 0.f;
        #pragma unroll
        for (int g2 = 0; g2 < 8; g2++) tot += red[g2][t];
        g_mmean2[(b * 8 + gg) * 32 + t] = tot;
    }
}

// ====================================================================
// K4 fused: mean -> fc1+gelu (4x parallel) -> fc2 -> softmax.
// ====================================================================
__global__ __launch_bounds__(512) void k4_fused(
    const float* __restrict__ fc1w, const float* __restrict__ fc1b,
    const float* __restrict__ fc2w, const float* __restrict__ fc2b,
    const float* __restrict__ P0,   const float* __restrict__ pb0,
    const float* __restrict__ P1,   const float* __restrict__ pb1)
{
    __shared__ float asm_[512];
    __shared__ float hsm[128];
    __shared__ float fsm[1536];
    __shared__ float mm[32];
    const int b = blockIdx.x, t = threadIdx.x;

    if (t < 32) {
        float tot = 0.f;
        #pragma unroll
        for (int gg = 0; gg < 8; gg++) tot += g_mmean2[(b * 8 + gg) * 32 + t];
        mm[t] = tot;
    }
    __syncthreads();

    float s = 0.f;
    #pragma unroll 8
    for (int tl = 0; tl < 64; tl++) s += g_part[(size_t)(b*64 + tl) * 512 + t];
    float hw = 0.f;
    #pragma unroll
    for (int i = 0; i < 16; i++) {
        hw += mm[i]      * P0[i*512 + t];
        hw += mm[16 + i] * P1[i*512 + t];
    }
    asm_[t] = (s + hw) * (1.0f / 4096.0f) + pb0[t] + pb1[t];
    __syncthreads();

    {
        const int n = t >> 2, l4 = t & 3;
        const int k0 = l4 * 128;
        float acc = 0.f;
        #pragma unroll 8
        for (int k = 0; k < 128; k++) acc += asm_[k0 + k] * fc1w[(k0 + k) * 128 + n];
        acc += __shfl_xor_sync(0xffffffffu, acc, 1, 4);
        acc += __shfl_xor_sync(0xffffffffu, acc, 2, 4);
        if (l4 == 0) {
            acc += fc1b[n];
            hsm[n] = 0.5f * acc * (1.0f + erff(acc * 0.70710678118654752f));
        }
    }
    __syncthreads();

    #pragma unroll
    for (int r = 0; r < 3; r++) {
        int n = t + r * 512;
        float acc = fc2b[n];
        #pragma unroll 8
        for (int j = 0; j < 128; j++) acc += hsm[j] * fc2w[j*1536 + n];
        fsm[n] = acc;
    }
    __syncthreads();

    float v0 = fsm[t*3], v1 = fsm[t*3+1], v2 = fsm[t*3+2];
    float mx = fmaxf(v0, fmaxf(v1, v2));
    float e0 = expf(v0-mx), e1 = expf(v1-mx), e2 = expf(v2-mx);
    float inv = 1.0f / (e0 + e1 + e2);
    g_a3[(0*16 + b)*512 + t] = e0 * inv;
    g_a3[(1*16 + b)*512 + t] = e1 * inv;
    g_a3[(2*16 + b)*512 + t] = e2 * inv;
}

// ====================================================================
// K5w2: per-batch B cols 0..511: Bmat[b][n][k] = fp16(a2_b[k] * WtT[n][k]).
// ====================================================================
__global__ __launch_bounds__(256) void k5w2_scale()
{
    __shared__ float a2s[512];
    const int b = blockIdx.x;
    const int t = threadIdx.x;
    const int n = blockIdx.y * 8 + (t >> 5);
    const int kb = (t & 31) * 16;

    for (int k = t; k < 512; k += 256) a2s[k] = g_a3[(size_t)(32 + b)*512 + k];
    __syncthreads();

    const float* src = g_WtT + (size_t)n * 512 + kb;
    __half* dst = g_Bmat + ((size_t)b * 512 + n) * AK + kb;
    #pragma unroll
    for (int q = 0; q < 4; q++) {
        float4 w = *(const float4*)(src + q * 4);
        __half h0 = __float2half_rn(w.x * a2s[kb + q*4 + 0]);
        __half h1 = __float2half_rn(w.y * a2s[kb + q*4 + 1]);
        __half h2 = __float2half_rn(w.z * a2s[kb + q*4 + 2]);
        __half h3 = __float2half_rn(w.w * a2s[kb + q*4 + 3]);
        __half2 p0 = __halves2half2(h0, h1), p1 = __halves2half2(h2, h3);
        *(uint2*)(dst + q * 4) = make_uint2(*(uint32_t*)&p0, *(uint32_t*)&p1);
    }
}

// ====================================================================
// K6: per-batch reduced weights Q_b (32x512) -> Bmat cols 512..543 (fp16)
// + zero-pad cols 544..575, plus fused bias.
// ====================================================================
__global__ __launch_bounds__(256) void k6_prep(
    const float* __restrict__ P0, const float* __restrict__ pb0,
    const float* __restrict__ P1, const float* __restrict__ pb1,
    const float* __restrict__ P,  const float* __restrict__ pb)
{
    extern __shared__ float k6sm[];
    const int b = blockIdx.x, t = threadIdx.x;
    const int ig = t >> 6;
    const int nn = t & 63;
    const int n = blockIdx.y * 64 + nn;
    const float* a0 = g_a3 + (size_t)b * 512;
    const float* a1 = g_a3 + (size_t)(16 + b) * 512;

    for (int e = t; e < 8192; e += 256) {
        int ch = e & 511;
        k6sm[e]        = P0[e] * a0[ch];
        k6sm[8192 + e] = P1[e] * a1[ch];
    }
    for (int ch = t; ch < 512; ch += 256)
        k6sm[16384 + ch] = pb0[ch]*a0[ch] + pb1[ch]*a1[ch];
    __syncthreads();

    const float* sPa = k6sm + (ig >= 2 ? 8192 : 0) + ((ig & 1) * 8) * 512;

    float acc8[8];
    #pragma unroll
    for (int j = 0; j < 8; j++) acc8[j] = 0.f;
    float bias = 0.f;

    for (int ch = 0; ch < 512; ch += 4) {
        float p0 = P[(size_t)(ch+0)*512 + n];
        float p1 = P[(size_t)(ch+1)*512 + n];
        float p2 = P[(size_t)(ch+2)*512 + n];
        float p3 = P[(size_t)(ch+3)*512 + n];
        if (ig == 0) {
            float4 sv = *(const float4*)&k6sm[16384 + ch];
            bias += sv.x*p0 + sv.y*p1 + sv.z*p2 + sv.w*p3;
        }
        #pragma unroll
        for (int j = 0; j < 8; j++) {
            float4 v = *(const float4*)&sPa[j*512 + ch];
            acc8[j] += v.x*p0 + v.y*p1 + v.z*p2 + v.w*p3;
        }
    }

    if (ig == 0) g_bias[(size_t)b*512 + n] = pb[n] + bias;
    __half* q = g_Bmat + ((size_t)b*512 + n) * AK + 512 + ig * 8;
    #pragma unroll
    for (int j = 0; j < 8; j++) q[j] = __float2half_rn(acc8[j]);
    *(uint4*)(g_Bmat + ((size_t)b*512 + n) * AK + 544 + ig * 8) = make_uint4(0,0,0,0);
}

// ====================================================================
// K5a-mini: g_mixed fp32 -> fp16 into A cols 512..543 + zero cols 544..575.
// ====================================================================
__global__ __launch_bounds__(256) void k5a_mix()
{
    const int gid = blockIdx.x * 256 + threadIdx.x;
    const int p  = gid >> 3;
    const int kq = (gid & 7) << 2;
    float4 m = *(const float4*)(g_mixed + (size_t)p * 32 + kq);
    __half2 h0 = __halves2half2(__float2half_rn(m.x), __float2half_rn(m.y));
    __half2 h1 = __halves2half2(__float2half_rn(m.z), __float2half_rn(m.w));
    *(uint2*)(g_Ahi + (size_t)p * AK + 512 + kq) = make_uint2(*(uint32_t*)&h0, *(uint32_t*)&h1);
    *(uint2*)(g_Ahi + (size_t)p * AK + 544 + kq) = make_uint2(0u, 0u);
}

// ====================================================================
// K5b: fp16 single-pass HMMA GEMM, 2 CTAs/SM (unchanged from best).
// ====================================================================
#define K5B_STG 32768u

__global__ __launch_bounds__(256, 2) void k5b_gemm(float* __restrict__ out)
{
    extern __shared__ char dsm[];
    const uint32_t base = smem_u32(dsm);

    const int tid  = threadIdx.x;
    const int wid  = tid >> 5;
    const int lane = tid & 31;
    const int nbase = blockIdx.x * 128;
    const int mbase = blockIdx.y * 128;
    const int b = mbase >> 12;
    const int wm = (wid >> 2) * 64;
    const int wn = (wid & 3) * 32;

    float acc[4][4][4];
    #pragma unroll
    for (int i = 0; i < 4; i++)
        #pragma unroll
        for (int j = 0; j < 4; j++)
            #pragma unroll
            for (int q = 0; q < 4; q++) acc[i][j][q] = 0.f;

    auto fill = [&](int s, int ch) {
        const uint32_t st = base + (uint32_t)s * K5B_STG;
        const int k0 = ch * 64;
        #pragma unroll
        for (int r = 0; r < 4; r++) {
            int idx = tid + r * 256;
            int row = idx >> 3, c = idx & 7;
            uint32_t dst = st + row * 128 + (((c ^ (row & 7)) & 7) << 4);
            CP_ASYNC16(dst, g_Ahi + (size_t)(mbase + row) * AK + k0 + c * 8);
        }
        #pragma unroll
        for (int r = 0; r < 4; r++) {
            int idx = tid + r * 256;
            int row = idx >> 3, c = idx & 7;
            uint32_t dst = st + 16384u + row * 128 + (((c ^ (row & 7)) & 7) << 4);
            CP_ASYNC16(dst, g_Bmat + ((size_t)b * 512 + nbase + row) * AK + k0 + c * 8);
        }
        CP_COMMIT();
    };

    fill(0, 0);
    fill(1, 1);

    for (int ch = 0; ch < 9; ch++) {
        const int s = ch % 3;
        const uint32_t st = base + (uint32_t)s * K5B_STG;
        if (ch == 8) { CP_WAIT0(); } else { CP_WAIT1(); }
        __syncthreads();
        if (ch + 2 <= 8) fill((ch + 2) % 3, ch + 2);

        #pragma unroll
        for (int kk = 0; kk < 4; kk++) {
            const int cb = 2 * kk + (lane >> 4);
            uint32_t bfr[4][2];
            #pragma unroll
            for (int j = 0; j < 2; j++) {
                int row = wn + j * 16 + (lane & 15);
                uint32_t r0, r1, r2, r3;
                LDMATRIX_X4(r0, r1, r2, r3,
                            st + 16384u + row * 128 + (((cb ^ (row & 7)) & 7) << 4));
                bfr[2*j][0] = r0;   bfr[2*j][1] = r2;
                bfr[2*j+1][0] = r1; bfr[2*j+1][1] = r3;
            }
            uint32_t a[4][4];
            #pragma unroll
            for (int i = 0; i < 4; i++) {
                int row = wm + i * 16 + (lane & 15);
                LDMATRIX_X4(a[i][0], a[i][1], a[i][2], a[i][3],
                            st + row * 128 + (((cb ^ (row & 7)) & 7) << 4));
            }
            #pragma unroll
            for (int i = 0; i < 4; i++)
                #pragma unroll
                for (int j = 0; j < 4; j++)
                    MMA_FP16(acc[i][j][0], acc[i][j][1], acc[i][j][2], acc[i][j][3],
                             a[i][0], a[i][1], a[i][2], a[i][3], bfr[j][0], bfr[j][1]);
        }
    }

    const float* bias = g_bias + (size_t)b * 512;
    #pragma unroll
    for (int i = 0; i < 4; i++) {
        const int r0 = mbase + wm + i * 16 + (lane >> 2);
        #pragma unroll
        for (int j = 0; j < 4; j++) {
            const int col = nbase + wn + j * 8 + (lane & 3) * 2;
            const float2 bb = *(const float2*)(bias + col);
            float2 o0 = make_float2(acc[i][j][0] + bb.x, acc[i][j][1] + bb.y);
            float2 o1 = make_float2(acc[i][j][2] + bb.x, acc[i][j][3] + bb.y);
            *(float2*)(out + (size_t)r0 * 512 + col)       = o0;
            *(float2*)(out + (size_t)(r0 + 8) * 512 + col) = o1;
        }
    }
}

// ====================================================================
extern "C" void kernel_launch(void* const* d_in, const int* in_sizes, int n_in,
                              void* d_out, int out_size)
{
    (void)in_sizes; (void)n_in; (void)out_size;
    const float* x       = (const float*)d_in[0];
    const float* mh_pinw = (const float*)d_in[1];
    const float* mh_pinb = (const float*)d_in[2];
    const float* mh_fw   = (const float*)d_in[3];
    const float* mh_fb   = (const float*)d_in[4];
    const float* mh_pow  = (const float*)d_in[5];
    const float* mh_pob  = (const float*)d_in[6];
    const float* mw_pinw = (const float*)d_in[7];
    const float* mw_pinb = (const float*)d_in[8];
    const float* mw_fw   = (const float*)d_in[9];
    const float* mw_fb   = (const float*)d_in[10];
    const float* mw_pow  = (const float*)d_in[11];
    const float* mw_pob  = (const float*)d_in[12];
    const float* c_w     = (const float*)d_in[13];
    const float* c_b     = (const float*)d_in[14];
    const float* fc1w    = (const float*)d_in[15];
    const float* fc1b    = (const float*)d_in[16];
    const float* fc2w    = (const float*)d_in[17];
    const float* fc2b    = (const float*)d_in[18];
    const float* projw   = (const float*)d_in[19];
    const float* projb   = (const float*)d_in[20];
    float* out = (float*)d_out;

    const int k2_smem  = 128 * 129 * sizeof(float);   // 66048 B
    const int k6_smem  = (16384 + 512) * 4;           // 67584 B
    const int k5b_smem = 3 * (int)K5B_STG;            // 98304 B
    cudaFuncSetAttribute(k2_mix,   cudaFuncAttributeMaxDynamicSharedMemorySize, k2_smem);
    cudaFuncSetAttribute(k6_prep,  cudaFuncAttributeMaxDynamicSharedMemorySize, k6_smem);
    cudaFuncSetAttribute(k5b_gemm, cudaFuncAttributeMaxDynamicSharedMemorySize, k5b_smem);

    // Order: k1 is launch #4 -> captured by ncu next round.
    k3_mixc<<<1024, 256>>>(x, c_w, c_b, 0);
    k5w1_transpose<<<dim3(16, 16), 256>>>(projw);
    k3_mixc<<<1024, 256>>>(x, c_w, c_b, 1024);
    k1_proj_in<<<512, 256>>>(x, mh_pinw, mh_pinb, mw_pinw, mw_pinb);
    k2_mix<<<256, 256, k2_smem>>>(mh_fw, mh_fb, mw_fw, mw_fb);
    k2m_mean<<<dim3(16, 8), 256>>>();
    k4_fused<<<16, 512>>>(fc1w, fc1b, fc2w, fc2b, mh_pow, mh_pob, mw_pow, mw_pob);
    k5w2_scale<<<dim3(16, 64), 256>>>();
    k6_prep<<<dim3(16, 8), 256, k6_smem>>>(mh_pow, mh_pob, mw_pow, mw_pob, projw, projb);
    k5a_mix<<<2048, 256>>>();
    k5b_gemm<<<dim3(4, 512), 256, k5b_smem>>>(out);
}

// round 16
// speedup vs baseline: 1.1847x; 1.1847x over previous
#include <cuda_runtime.h>
#include <cuda_fp16.h>
#include <math.h>
#include <stdint.h>

// Problem dims
#define NPIX (16*64*64)      // 65536 pixels
#define DIMC 512
#define AK   576             // padded K: 512 (c) + 32 (mixed) + 32 (zeros)

// -------- scratch (device globals; no allocations allowed) --------
__device__ __align__(16) __half g_t[NPIX*32];       // proj_in outputs (fp16)
__device__ __align__(16) float g_mixed[NPIX*32];    // windowed-mixing outputs (fp32)
__device__ __align__(16) float g_part[1024*DIMC];   // partial sums of c (spatial mean)
__device__ __align__(16) float g_mmean2[16*8*32];   // per-(batch,slab) sums of mixed
__device__ __align__(16) float g_a3[3*16*DIMC];     // softmax reweight coefficients
__device__ __align__(16) float g_bias[16*DIMC];     // per-batch fused bias vector
__device__ __align__(16) float g_WtT[DIMC*DIMC];    // proj_w^T fp32 [n][k]
// fp16 operands for the final GEMM (K padded to 576)
__device__ __align__(16) __half g_Ahi[NPIX*AK];       // A plane [m][576]
__device__ __align__(16) __half g_Bmat[16*DIMC*AK];   // per-batch B^T [b][n][576]

// ---------------- PTX helpers (portable sm_80+ subset) ----------------
__device__ __forceinline__ uint32_t smem_u32(const void* p) {
    uint32_t a;
    asm("{ .reg .u64 t; cvta.to.shared.u64 t, %1; cvt.u32.u64 %0, t; }" : "=r"(a) : "l"(p));
    return a;
}
#define CP_ASYNC16(dst, src) \
    asm volatile("cp.async.cg.shared.global [%0], [%1], 16;" :: "r"(dst), "l"(src))
#define CP_COMMIT() asm volatile("cp.async.commit_group;" ::: "memory")
#define CP_WAIT1()  asm volatile("cp.async.wait_group 1;" ::: "memory")
#define CP_WAIT0()  asm volatile("cp.async.wait_group 0;" ::: "memory")

#define LDMATRIX_X4(r0, r1, r2, r3, addr) \
    asm volatile("ldmatrix.sync.aligned.m8n8.x4.shared.b16 {%0,%1,%2,%3}, [%4];" \
                 : "=r"(r0), "=r"(r1), "=r"(r2), "=r"(r3) : "r"(addr))

#define MMA_FP16(c0, c1, c2, c3, a0, a1, a2, a3, b0, b1) \
    asm volatile("mma.sync.aligned.m16n8k16.row.col.f32.f16.f16.f32 " \
                 "{%0,%1,%2,%3}, {%4,%5,%6,%7}, {%8,%9}, {%0,%1,%2,%3};" \
                 : "+f"(c0), "+f"(c1), "+f"(c2), "+f"(c3) \
                 : "r"(a0), "r"(a1), "r"(a2), "r"(a3), "r"(b0), "r"(b1))

// ====================================================================
// K5w1: fp32 transpose of proj_w -> g_WtT[n][k]. Tiled via smem.
// ====================================================================
__global__ __launch_bounds__(256) void k5w1_transpose(const float* __restrict__ pw)
{
    __shared__ float ts[32][33];
    const int k0 = blockIdx.x * 32;
    const int n0 = blockIdx.y * 32;
    const int t = threadIdx.x;
    const int tr = t >> 5, tc = t & 31;
    #pragma unroll
    for (int rep = 0; rep < 4; rep++) {
        int row = tr + rep * 8;
        ts[row][tc] = pw[(size_t)(k0 + row) * 512 + n0 + tc];
    }
    __syncthreads();
    #pragma unroll
    for (int rep = 0; rep < 4; rep++) {
        int row = tr + rep * 8;
        g_WtT[(size_t)(n0 + row) * 512 + k0 + tc] = ts[tc][row];
    }
}

// ====================================================================
// K1: fused proj_in via fp16 HMMA.  t[m][0:32] = x[m][:] @ [w0|w1] + b.
// CTA = 128 M x 32 N, grid 512, 256 thr (8 warps of 16M x 32N).
// x fp32 loaded in regs per k64-chunk, converted fp16 -> smem (2 bufs),
// weights converted once to smem. Output g_t stored fp16.
// Smem: Bs 32x520 halfs (33280 B) | Ah 2 x 128x64 halfs (2x16384 B).
// ====================================================================
#define K1_BS_BYTES 33280u

__global__ __launch_bounds__(256) void k1_proj_in(
    const float* __restrict__ x,
    const float* __restrict__ w0, const float* __restrict__ b0,
    const float* __restrict__ w1, const float* __restrict__ b1)
{
    extern __shared__ char k1sm[];
    __half* Bs = (__half*)k1sm;                       // [32][520]
    const uint32_t bs_base = smem_u32(k1sm);
    const uint32_t ah_base = bs_base + K1_BS_BYTES;   // 2 buffers of 16384 B

    const int tid  = threadIdx.x;
    const int wid  = tid >> 5;
    const int lane = tid & 31;
    const int mbase = blockIdx.x * 128;
    const int wm = wid * 16;

    // fill Bs: B[n][k] = (n<16 ? w0[k*16+n] : w1[k*16+n-16]) fp16
    for (int i = tid; i < 32 * 512; i += 256) {
        int n = i >> 9, k = i & 511;
        float v = (n < 16) ? w0[k * 16 + n] : w1[k * 16 + (n - 16)];
        Bs[n * 520 + k] = __float2half_rn(v);
    }

    // A chunk register prefetch: 4 (row,c) units x 8 floats
    float4 pa[4][2];
    auto loadA = [&](int ch) {
        const int k0 = ch * 64;
        #pragma unroll
        for (int r = 0; r < 4; r++) {
            int idx = tid + r * 256;
            int row = idx >> 3, c = idx & 7;
            const float4* s = (const float4*)(x + (size_t)(mbase + row) * 512 + k0 + c * 8);
            pa[r][0] = s[0];
            pa[r][1] = s[1];
        }
    };
    auto storeA = [&](int buf) {
        const uint32_t ab = ah_base + (uint32_t)buf * 16384u;
        #pragma unroll
        for (int r = 0; r < 4; r++) {
            int idx = tid + r * 256;
            int row = idx >> 3, c = idx & 7;
            __half2 h0 = __halves2half2(__float2half_rn(pa[r][0].x), __float2half_rn(pa[r][0].y));
            __half2 h1 = __halves2half2(__float2half_rn(pa[r][0].z), __float2half_rn(pa[r][0].w));
            __half2 h2 = __halves2half2(__float2half_rn(pa[r][1].x), __float2half_rn(pa[r][1].y));
            __half2 h3 = __halves2half2(__float2half_rn(pa[r][1].z), __float2half_rn(pa[r][1].w));
            uint4 v = make_uint4(*(uint32_t*)&h0, *(uint32_t*)&h1, *(uint32_t*)&h2, *(uint32_t*)&h3);
            *(uint4*)(k1sm + (K1_BS_BYTES + buf * 16384u) + row * 128 + (((c ^ (row & 7)) & 7) << 4)) = v;
        }
        (void)ab;
    };

    float acc[4][4];
    #pragma unroll
    for (int j = 0; j < 4; j++)
        #pragma unroll
        for (int q = 0; q < 4; q++) acc[j][q] = 0.f;

    loadA(0);
    storeA(0);
    loadA(1);
    __syncthreads();          // Bs + buf0 visible

    for (int ch = 0; ch < 8; ch++) {
        const int buf = ch & 1;
        if (ch < 7) {
            storeA(1 - buf);
            if (ch < 6) loadA(ch + 2);
        }
        // MMA on buffer `buf`
        const uint32_t ab = ah_base + (uint32_t)buf * 16384u;
        #pragma unroll
        for (int kk = 0; kk < 4; kk++) {
            const int cb = 2 * kk + (lane >> 4);
            uint32_t a0, a1, a2, a3;
            {
                int row = wm + (lane & 15);
                LDMATRIX_X4(a0, a1, a2, a3, ab + row * 128 + (((cb ^ (row & 7)) & 7) << 4));
            }
            uint32_t bfr[4][2];
            #pragma unroll
            for (int j = 0; j < 2; j++) {
                int row = j * 16 + (lane & 15);
                uint32_t r0, r1, r2, r3;
                LDMATRIX_X4(r0, r1, r2, r3,
                            bs_base + row * 1040 + ch * 128 + kk * 32 + ((lane >> 4) << 4));
                bfr[2*j][0] = r0;   bfr[2*j][1] = r2;
                bfr[2*j+1][0] = r1; bfr[2*j+1][1] = r3;
            }
            #pragma unroll
            for (int j = 0; j < 4; j++)
                MMA_FP16(acc[j][0], acc[j][1], acc[j][2], acc[j][3],
                         a0, a1, a2, a3, bfr[j][0], bfr[j][1]);
        }
        __syncthreads();
    }

    // epilogue: add bias, store fp16 to g_t
    const int r0 = mbase + wm + (lane >> 2);
    #pragma unroll
    for (int j = 0; j < 4; j++) {
        const int col = j * 8 + (lane & 3) * 2;
        const float bb0 = (col < 16) ? b0[col]     : b1[col - 16];
        const float bb1 = (col + 1 < 16) ? b0[col + 1] : b1[col + 1 - 16];
        __half2 o0 = __halves2half2(__float2half_rn(acc[j][0] + bb0),
                                    __float2half_rn(acc[j][1] + bb1));
        __half2 o1 = __halves2half2(__float2half_rn(acc[j][2] + bb0),
                                    __float2half_rn(acc[j][3] + bb1));
        *(__half2*)(g_t + (size_t)r0 * 32 + col)       = o0;
        *(__half2*)(g_t + (size_t)(r0 + 8) * 32 + col) = o1;
    }
}

// ====================================================================
// K2: windowed mixing, 256 threads = 2 window-groups sharing the
// cached weight matrix. g_t now fp16.
// ====================================================================
__global__ __launch_bounds__(256) void k2_mix(
    const float* __restrict__ fw0, const float* __restrict__ fb0,
    const float* __restrict__ fw1, const float* __restrict__ fb1)
{
    extern __shared__ float sm[];
    float (*Wsm)[129] = (float (*)[129])sm;
    __shared__ float vst[2][128][4];

    const int mix  = blockIdx.x >> 7;
    const int head = (blockIdx.x >> 4) & 7;
    const int wt   = blockIdx.x & 15;
    const float* fw = mix ? fw1 : fw0;
    const float* fb = mix ? fb1 : fb0;
    const int tt = threadIdx.x;
    const int t   = tt & 127;
    const int grp = tt >> 7;

    for (int i = tt; i < 128 * 128; i += 256) {
        int d = i & 127;
        int f = i >> 7;
        Wsm[d][f] = fw[f * 1024 + head * 128 + d];
    }
    const int ch = mix * 16 + head * 2 + (t & 1);
    const float fbv = fb[t];
    __syncthreads();

    for (int pass = 0; pass < 8; pass++) {
        int px[4];
        #pragma unroll
        for (int j = 0; j < 4; j++) {
            int wg = wt * 64 + pass * 8 + grp * 4 + j;
            int Bb = wg >> 4, nw = wg & 15;
            int b = Bb >> 2, n1 = (Bb >> 1) & 1, n2 = Bb & 1;
            int row, col;
            if (mix == 0) { row = 2 * (t >> 2) + n1;          col = 4 * nw + 2 * ((t >> 1) & 1) + n2; }
            else          { row = 4 * nw + 2 * (t >> 6) + n1; col = 2 * ((t >> 1) & 31) + n2; }
            int pix = (b * 64 + row) * 64 + col;
            px[j] = pix;
            vst[grp][t][j] = __half2float(g_t[(size_t)pix * 32 + ch]);
        }
        __syncthreads();
        float a0 = fbv, a1 = fbv, a2 = fbv, a3 = fbv;
        #pragma unroll 8
        for (int d = 0; d < 128; d++) {
            float4 vv = *(const float4*)&vst[grp][d][0];
            float wv = Wsm[d][t];
            a0 += vv.x * wv; a1 += vv.y * wv; a2 += vv.z * wv; a3 += vv.w * wv;
        }
        g_mixed[(size_t)px[0] * 32 + ch] = a0;
        g_mixed[(size_t)px[1] * 32 + ch] = a1;
        g_mixed[(size_t)px[2] * 32 + ch] = a2;
        g_mixed[(size_t)px[3] * 32 + ch] = a3;
        __syncthreads();
    }
}

// ====================================================================
// K3: MixC only -> fp16 A plane (cols 0..511) + partial sums of c.
// ====================================================================
__global__ __launch_bounds__(256) void k3_mixc(
    const float* __restrict__ x,
    const float* __restrict__ cwg, const float* __restrict__ cbg)
{
    const int bx = blockIdx.x;
    const int b = bx >> 7;
    const int rem = bx & 127;
    const int tile = rem >> 1;
    const int chH = rem & 1;
    const int ty = tile >> 3, tx = tile & 7;
    const int ch = chH * 256 + threadIdx.x;

    float cwr[16], cbr[4];
    #pragma unroll
    for (int i = 0; i < 16; i++) cwr[i] = cwg[ch*16 + i];
    #pragma unroll
    for (int p = 0; p < 4; p++) cbr[p] = cbg[ch*4 + p];

    float ssum = 0.f;
    #pragma unroll 2
    for (int bi = 0; bi < 16; bi++) {
        int brow = bi >> 2, bcol = bi & 3;
        int r0 = ty*8 + brow*2, c0 = tx*8 + bcol*2;
        float x4[4];
        #pragma unroll
        for (int q = 0; q < 4; q++) {
            int q1 = q >> 1, q2 = q & 1;
            x4[q] = x[(size_t)((b*64 + r0 + q1) * 64 + c0 + q2) * 512 + ch];
        }
        #pragma unroll
        for (int p = 0; p < 4; p++) {
            int p1 = p >> 1, p2 = p & 1;
            float cv = cbr[p];
            #pragma unroll
            for (int q = 0; q < 4; q++) cv += x4[q] * cwr[q*4 + p];
            const size_t pix = (size_t)((b*64 + r0 + p1) * 64 + c0 + p2);
            g_Ahi[pix * AK + ch] = __float2half_rn(cv);
            ssum += cv;
        }
    }
    g_part[(size_t)(b*64 + tile) * 512 + ch] = ssum;
}

// ====================================================================
// K2m: per-(batch, 512-pixel slab) sums of g_mixed -> g_mmean2.
// ====================================================================
__global__ __launch_bounds__(256) void k2m_mean()
{
    __shared__ float red[8][32];
    const int b = blockIdx.x, gg = blockIdx.y;
    const int t = threadIdx.x;
    const int cc = t & 31, sub = t >> 5;
    float s = 0.f;
    const float* src = g_mixed + ((size_t)(b * 4096 + gg * 512 + sub * 64)) * 32 + cc;
    #pragma unroll 8
    for (int i = 0; i < 64; i++) s += src[(size_t)i * 32];
    red[sub][cc] = s;
    __syncthreads();
    if (t < 32) {
        float tot = 0.f;
        #pragma unroll
        for (int g2 = 0; g2 < 8; g2++) tot += red[g2][t];
        g_mmean2[(b * 8 + gg) * 32 + t] = tot;
    }
}

// ====================================================================
// K4 fused: mean -> fc1+gelu (4x parallel) -> fc2 -> softmax.
// ====================================================================
__global__ __launch_bounds__(512) void k4_fused(
    const float* __restrict__ fc1w, const float* __restrict__ fc1b,
    const float* __restrict__ fc2w, const float* __restrict__ fc2b,
    const float* __restrict__ P0,   const float* __restrict__ pb0,
    const float* __restrict__ P1,   const float* __restrict__ pb1)
{
    __shared__ float asm_[512];
    __shared__ float hsm[128];
    __shared__ float fsm[1536];
    __shared__ float mm[32];
    const int b = blockIdx.x, t = threadIdx.x;

    if (t < 32) {
        float tot = 0.f;
        #pragma unroll
        for (int gg = 0; gg < 8; gg++) tot += g_mmean2[(b * 8 + gg) * 32 + t];
        mm[t] = tot;
    }
    __syncthreads();

    float s = 0.f;
    #pragma unroll 8
    for (int tl = 0; tl < 64; tl++) s += g_part[(size_t)(b*64 + tl) * 512 + t];
    float hw = 0.f;
    #pragma unroll
    for (int i = 0; i < 16; i++) {
        hw += mm[i]      * P0[i*512 + t];
        hw += mm[16 + i] * P1[i*512 + t];
    }
    asm_[t] = (s + hw) * (1.0f / 4096.0f) + pb0[t] + pb1[t];
    __syncthreads();

    {
        const int n = t >> 2, l4 = t & 3;
        const int k0 = l4 * 128;
        float acc = 0.f;
        #pragma unroll 8
        for (int k = 0; k < 128; k++) acc += asm_[k0 + k] * fc1w[(k0 + k) * 128 + n];
        acc += __shfl_xor_sync(0xffffffffu, acc, 1, 4);
        acc += __shfl_xor_sync(0xffffffffu, acc, 2, 4);
        if (l4 == 0) {
            acc += fc1b[n];
            hsm[n] = 0.5f * acc * (1.0f + erff(acc * 0.70710678118654752f));
        }
    }
    __syncthreads();

    #pragma unroll
    for (int r = 0; r < 3; r++) {
        int n = t + r * 512;
        float acc = fc2b[n];
        #pragma unroll 8
        for (int j = 0; j < 128; j++) acc += hsm[j] * fc2w[j*1536 + n];
        fsm[n] = acc;
    }
    __syncthreads();

    float v0 = fsm[t*3], v1 = fsm[t*3+1], v2 = fsm[t*3+2];
    float mx = fmaxf(v0, fmaxf(v1, v2));
    float e0 = expf(v0-mx), e1 = expf(v1-mx), e2 = expf(v2-mx);
    float inv = 1.0f / (e0 + e1 + e2);
    g_a3[(0*16 + b)*512 + t] = e0 * inv;
    g_a3[(1*16 + b)*512 + t] = e1 * inv;
    g_a3[(2*16 + b)*512 + t] = e2 * inv;
}

// ====================================================================
// K5w2: per-batch B cols 0..511: Bmat[b][n][k] = fp16(a2_b[k] * WtT[n][k]).
// ====================================================================
__global__ __launch_bounds__(256) void k5w2_scale()
{
    __shared__ float a2s[512];
    const int b = blockIdx.x;
    const int t = threadIdx.x;
    const int n = blockIdx.y * 8 + (t >> 5);
    const int kb = (t & 31) * 16;

    for (int k = t; k < 512; k += 256) a2s[k] = g_a3[(size_t)(32 + b)*512 + k];
    __syncthreads();

    const float* src = g_WtT + (size_t)n * 512 + kb;
    __half* dst = g_Bmat + ((size_t)b * 512 + n) * AK + kb;
    #pragma unroll
    for (int q = 0; q < 4; q++) {
        float4 w = *(const float4*)(src + q * 4);
        __half h0 = __float2half_rn(w.x * a2s[kb + q*4 + 0]);
        __half h1 = __float2half_rn(w.y * a2s[kb + q*4 + 1]);
        __half h2 = __float2half_rn(w.z * a2s[kb + q*4 + 2]);
        __half h3 = __float2half_rn(w.w * a2s[kb + q*4 + 3]);
        __half2 p0 = __halves2half2(h0, h1), p1 = __halves2half2(h2, h3);
        *(uint2*)(dst + q * 4) = make_uint2(*(uint32_t*)&p0, *(uint32_t*)&p1);
    }
}

// ====================================================================
// K6: per-batch reduced weights Q_b (32x512) -> Bmat cols 512..543 (fp16)
// + zero-pad cols 544..575, plus fused bias.
// ====================================================================
__global__ __launch_bounds__(256) void k6_prep(
    const float* __restrict__ P0, const float* __restrict__ pb0,
    const float* __restrict__ P1, const float* __restrict__ pb1,
    const float* __restrict__ P,  const float* __restrict__ pb)
{
    extern __shared__ float k6sm[];
    const int b = blockIdx.x, t = threadIdx.x;
    const int ig = t >> 6;
    const int nn = t & 63;
    const int n = blockIdx.y * 64 + nn;
    const float* a0 = g_a3 + (size_t)b * 512;
    const float* a1 = g_a3 + (size_t)(16 + b) * 512;

    for (int e = t; e < 8192; e += 256) {
        int ch = e & 511;
        k6sm[e]        = P0[e] * a0[ch];
        k6sm[8192 + e] = P1[e] * a1[ch];
    }
    for (int ch = t; ch < 512; ch += 256)
        k6sm[16384 + ch] = pb0[ch]*a0[ch] + pb1[ch]*a1[ch];
    __syncthreads();

    const float* sPa = k6sm + (ig >= 2 ? 8192 : 0) + ((ig & 1) * 8) * 512;

    float acc8[8];
    #pragma unroll
    for (int j = 0; j < 8; j++) acc8[j] = 0.f;
    float bias = 0.f;

    for (int ch = 0; ch < 512; ch += 4) {
        float p0 = P[(size_t)(ch+0)*512 + n];
        float p1 = P[(size_t)(ch+1)*512 + n];
        float p2 = P[(size_t)(ch+2)*512 + n];
        float p3 = P[(size_t)(ch+3)*512 + n];
        if (ig == 0) {
            float4 sv = *(const float4*)&k6sm[16384 + ch];
            bias += sv.x*p0 + sv.y*p1 + sv.z*p2 + sv.w*p3;
        }
        #pragma unroll
        for (int j = 0; j < 8; j++) {
            float4 v = *(const float4*)&sPa[j*512 + ch];
            acc8[j] += v.x*p0 + v.y*p1 + v.z*p2 + v.w*p3;
        }
    }

    if (ig == 0) g_bias[(size_t)b*512 + n] = pb[n] + bias;
    __half* q = g_Bmat + ((size_t)b*512 + n) * AK + 512 + ig * 8;
    #pragma unroll
    for (int j = 0; j < 8; j++) q[j] = __float2half_rn(acc8[j]);
    *(uint4*)(g_Bmat + ((size_t)b*512 + n) * AK + 544 + ig * 8) = make_uint4(0,0,0,0);
}

// ====================================================================
// K5a-mini: g_mixed fp32 -> fp16 into A cols 512..543 + zero cols 544..575.
// ====================================================================
__global__ __launch_bounds__(256) void k5a_mix()
{
    const int gid = blockIdx.x * 256 + threadIdx.x;
    const int p  = gid >> 3;
    const int kq = (gid & 7) << 2;
    float4 m = *(const float4*)(g_mixed + (size_t)p * 32 + kq);
    __half2 h0 = __halves2half2(__float2half_rn(m.x), __float2half_rn(m.y));
    __half2 h1 = __halves2half2(__float2half_rn(m.z), __float2half_rn(m.w));
    *(uint2*)(g_Ahi + (size_t)p * AK + 512 + kq) = make_uint2(*(uint32_t*)&h0, *(uint32_t*)&h1);
    *(uint2*)(g_Ahi + (size_t)p * AK + 544 + kq) = make_uint2(0u, 0u);
}

// ====================================================================
// K5b: fp16 single-pass HMMA GEMM, 2 CTAs/SM (unchanged from best).
// ====================================================================
#define K5B_STG 32768u

__global__ __launch_bounds__(256, 2) void k5b_gemm(float* __restrict__ out)
{
    extern __shared__ char dsm[];
    const uint32_t base = smem_u32(dsm);

    const int tid  = threadIdx.x;
    const int wid  = tid >> 5;
    const int lane = tid & 31;
    const int nbase = blockIdx.x * 128;
    const int mbase = blockIdx.y * 128;
    const int b = mbase >> 12;
    const int wm = (wid >> 2) * 64;
    const int wn = (wid & 3) * 32;

    float acc[4][4][4];
    #pragma unroll
    for (int i = 0; i < 4; i++)
        #pragma unroll
        for (int j = 0; j < 4; j++)
            #pragma unroll
            for (int q = 0; q < 4; q++) acc[i][j][q] = 0.f;

    auto fill = [&](int s, int ch) {
        const uint32_t st = base + (uint32_t)s * K5B_STG;
        const int k0 = ch * 64;
        #pragma unroll
        for (int r = 0; r < 4; r++) {
            int idx = tid + r * 256;
            int row = idx >> 3, c = idx & 7;
            uint32_t dst = st + row * 128 + (((c ^ (row & 7)) & 7) << 4);
            CP_ASYNC16(dst, g_Ahi + (size_t)(mbase + row) * AK + k0 + c * 8);
        }
        #pragma unroll
        for (int r = 0; r < 4; r++) {
            int idx = tid + r * 256;
            int row = idx >> 3, c = idx & 7;
            uint32_t dst = st + 16384u + row * 128 + (((c ^ (row & 7)) & 7) << 4);
            CP_ASYNC16(dst, g_Bmat + ((size_t)b * 512 + nbase + row) * AK + k0 + c * 8);
        }
        CP_COMMIT();
    };

    fill(0, 0);
    fill(1, 1);

    for (int ch = 0; ch < 9; ch++) {
        const int s = ch % 3;
        const uint32_t st = base + (uint32_t)s * K5B_STG;
        if (ch == 8) { CP_WAIT0(); } else { CP_WAIT1(); }
        __syncthreads();
        if (ch + 2 <= 8) fill((ch + 2) % 3, ch + 2);

        #pragma unroll
        for (int kk = 0; kk < 4; kk++) {
            const int cb = 2 * kk + (lane >> 4);
            uint32_t bfr[4][2];
            #pragma unroll
            for (int j = 0; j < 2; j++) {
                int row = wn + j * 16 + (lane & 15);
                uint32_t r0, r1, r2, r3;
                LDMATRIX_X4(r0, r1, r2, r3,
                            st + 16384u + row * 128 + (((cb ^ (row & 7)) & 7) << 4));
                bfr[2*j][0] = r0;   bfr[2*j][1] = r2;
                bfr[2*j+1][0] = r1; bfr[2*j+1][1] = r3;
            }
            uint32_t a[4][4];
            #pragma unroll
            for (int i = 0; i < 4; i++) {
                int row = wm + i * 16 + (lane & 15);
                LDMATRIX_X4(a[i][0], a[i][1], a[i][2], a[i][3],
                            st + row * 128 + (((cb ^ (row & 7)) & 7) << 4));
            }
            #pragma unroll
            for (int i = 0; i < 4; i++)
                #pragma unroll
                for (int j = 0; j < 4; j++)
                    MMA_FP16(acc[i][j][0], acc[i][j][1], acc[i][j][2], acc[i][j][3],
                             a[i][0], a[i][1], a[i][2], a[i][3], bfr[j][0], bfr[j][1]);
        }
    }

    const float* bias = g_bias + (size_t)b * 512;
    #pragma unroll
    for (int i = 0; i < 4; i++) {
        const int r0 = mbase + wm + i * 16 + (lane >> 2);
        #pragma unroll
        for (int j = 0; j < 4; j++) {
            const int col = nbase + wn + j * 8 + (lane & 3) * 2;
            const float2 bb = *(const float2*)(bias + col);
            float2 o0 = make_float2(acc[i][j][0] + bb.x, acc[i][j][1] + bb.y);
            float2 o1 = make_float2(acc[i][j][2] + bb.x, acc[i][j][3] + bb.y);
            *(float2*)(out + (size_t)r0 * 512 + col)       = o0;
            *(float2*)(out + (size_t)(r0 + 8) * 512 + col) = o1;
        }
    }
}

// ====================================================================
extern "C" void kernel_launch(void* const* d_in, const int* in_sizes, int n_in,
                              void* d_out, int out_size)
{
    (void)in_sizes; (void)n_in; (void)out_size;
    const float* x       = (const float*)d_in[0];
    const float* mh_pinw = (const float*)d_in[1];
    const float* mh_pinb = (const float*)d_in[2];
    const float* mh_fw   = (const float*)d_in[3];
    const float* mh_fb   = (const float*)d_in[4];
    const float* mh_pow  = (const float*)d_in[5];
    const float* mh_pob  = (const float*)d_in[6];
    const float* mw_pinw = (const float*)d_in[7];
    const float* mw_pinb = (const float*)d_in[8];
    const float* mw_fw   = (const float*)d_in[9];
    const float* mw_fb   = (const float*)d_in[10];
    const float* mw_pow  = (const float*)d_in[11];
    const float* mw_pob  = (const float*)d_in[12];
    const float* c_w     = (const float*)d_in[13];
    const float* c_b     = (const float*)d_in[14];
    const float* fc1w    = (const float*)d_in[15];
    const float* fc1b    = (const float*)d_in[16];
    const float* fc2w    = (const float*)d_in[17];
    const float* fc2b    = (const float*)d_in[18];
    const float* projw   = (const float*)d_in[19];
    const float* projb   = (const float*)d_in[20];
    float* out = (float*)d_out;

    const int k1_smem  = (int)K1_BS_BYTES + 2 * 16384;  // 66048 B
    const int k2_smem  = 128 * 129 * sizeof(float);     // 66048 B
    const int k6_smem  = (16384 + 512) * 4;             // 67584 B
    const int k5b_smem = 3 * (int)K5B_STG;              // 98304 B
    cudaFuncSetAttribute(k1_proj_in, cudaFuncAttributeMaxDynamicSharedMemorySize, k1_smem);
    cudaFuncSetAttribute(k2_mix,     cudaFuncAttributeMaxDynamicSharedMemorySize, k2_smem);
    cudaFuncSetAttribute(k6_prep,    cudaFuncAttributeMaxDynamicSharedMemorySize, k6_smem);
    cudaFuncSetAttribute(k5b_gemm,   cudaFuncAttributeMaxDynamicSharedMemorySize, k5b_smem);

    // Order: k2 is launch #4 -> captured by ncu next round.
    k3_mixc<<<2048, 256>>>(x, c_w, c_b);
    k5w1_transpose<<<dim3(16, 16), 256>>>(projw);
    k1_proj_in<<<512, 256, k1_smem>>>(x, mh_pinw, mh_pinb, mw_pinw, mw_pinb);
    k2_mix<<<256, 256, k2_smem>>>(mh_fw, mh_fb, mw_fw, mw_fb);
    k2m_mean<<<dim3(16, 8), 256>>>();
    k4_fused<<<16, 512>>>(fc1w, fc1b, fc2w, fc2b, mh_pow, mh_pob, mw_pow, mw_pob);
    k5w2_scale<<<dim3(16, 64), 256>>>();
    k6_prep<<<dim3(16, 8), 256, k6_smem>>>(mh_pow, mh_pob, mw_pow, mw_pob, projw, projb);
    k5a_mix<<<2048, 256>>>();
    k5b_gemm<<<dim3(4, 512), 256, k5b_smem>>>(out);
}

// round 17
// speedup vs baseline: 1.1958x; 1.0093x over previous
#include <cuda_runtime.h>
#include <cuda_fp16.h>
#include <math.h>
#include <stdint.h>

// Problem dims
#define NPIX (16*64*64)      // 65536 pixels
#define DIMC 512
#define AK   576             // padded K: 512 (c) + 32 (mixed) + 32 (zeros)

// -------- scratch (device globals; no allocations allowed) --------
__device__ __align__(16) __half g_t[NPIX*32];       // proj_in outputs (fp16)
__device__ __align__(16) float g_mixed[NPIX*32];    // windowed-mixing outputs (fp32)
__device__ __align__(16) float g_part[1024*DIMC];   // partial sums of c (spatial mean)
__device__ __align__(16) float g_mmean2[16*8*32];   // per-(batch,slab) sums of mixed
__device__ __align__(16) float g_a3[3*16*DIMC];     // softmax reweight coefficients
__device__ __align__(16) float g_bias[16*DIMC];     // per-batch fused bias vector
__device__ __align__(16) float g_WtT[DIMC*DIMC];    // proj_w^T fp32 [n][k]
// fp16 operands for the final GEMM (K padded to 576)
__device__ __align__(16) __half g_Ahi[NPIX*AK];       // A plane [m][576]
__device__ __align__(16) __half g_Bmat[16*DIMC*AK];   // per-batch B^T [b][n][576]

// ---------------- PTX helpers (portable sm_80+ subset) ----------------
__device__ __forceinline__ uint32_t smem_u32(const void* p) {
    uint32_t a;
    asm("{ .reg .u64 t; cvta.to.shared.u64 t, %1; cvt.u32.u64 %0, t; }" : "=r"(a) : "l"(p));
    return a;
}
#define CP_ASYNC16(dst, src) \
    asm volatile("cp.async.cg.shared.global [%0], [%1], 16;" :: "r"(dst), "l"(src))
#define CP_COMMIT() asm volatile("cp.async.commit_group;" ::: "memory")
#define CP_WAIT1()  asm volatile("cp.async.wait_group 1;" ::: "memory")
#define CP_WAIT0()  asm volatile("cp.async.wait_group 0;" ::: "memory")

#define LDMATRIX_X4(r0, r1, r2, r3, addr) \
    asm volatile("ldmatrix.sync.aligned.m8n8.x4.shared.b16 {%0,%1,%2,%3}, [%4];" \
                 : "=r"(r0), "=r"(r1), "=r"(r2), "=r"(r3) : "r"(addr))

#define MMA_FP16(c0, c1, c2, c3, a0, a1, a2, a3, b0, b1) \
    asm volatile("mma.sync.aligned.m16n8k16.row.col.f32.f16.f16.f32 " \
                 "{%0,%1,%2,%3}, {%4,%5,%6,%7}, {%8,%9}, {%0,%1,%2,%3};" \
                 : "+f"(c0), "+f"(c1), "+f"(c2), "+f"(c3) \
                 : "r"(a0), "r"(a1), "r"(a2), "r"(a3), "r"(b0), "r"(b1))

// ====================================================================
// K5w1: fp32 transpose of proj_w -> g_WtT[n][k]. Tiled via smem.
// ====================================================================
__global__ __launch_bounds__(256) void k5w1_transpose(const float* __restrict__ pw)
{
    __shared__ float ts[32][33];
    const int k0 = blockIdx.x * 32;
    const int n0 = blockIdx.y * 32;
    const int t = threadIdx.x;
    const int tr = t >> 5, tc = t & 31;
    #pragma unroll
    for (int rep = 0; rep < 4; rep++) {
        int row = tr + rep * 8;
        ts[row][tc] = pw[(size_t)(k0 + row) * 512 + n0 + tc];
    }
    __syncthreads();
    #pragma unroll
    for (int rep = 0; rep < 4; rep++) {
        int row = tr + rep * 8;
        g_WtT[(size_t)(n0 + row) * 512 + k0 + tc] = ts[tc][row];
    }
}

// ====================================================================
// K1: fused proj_in via fp16 HMMA (unchanged from R16 win).
// ====================================================================
#define K1_BS_BYTES 33280u

__global__ __launch_bounds__(256) void k1_proj_in(
    const float* __restrict__ x,
    const float* __restrict__ w0, const float* __restrict__ b0,
    const float* __restrict__ w1, const float* __restrict__ b1)
{
    extern __shared__ char k1sm[];
    __half* Bs = (__half*)k1sm;                       // [32][520]
    const uint32_t bs_base = smem_u32(k1sm);
    const uint32_t ah_base = bs_base + K1_BS_BYTES;

    const int tid  = threadIdx.x;
    const int wid  = tid >> 5;
    const int lane = tid & 31;
    const int mbase = blockIdx.x * 128;
    const int wm = wid * 16;

    for (int i = tid; i < 32 * 512; i += 256) {
        int n = i >> 9, k = i & 511;
        float v = (n < 16) ? w0[k * 16 + n] : w1[k * 16 + (n - 16)];
        Bs[n * 520 + k] = __float2half_rn(v);
    }

    float4 pa[4][2];
    auto loadA = [&](int ch) {
        const int k0 = ch * 64;
        #pragma unroll
        for (int r = 0; r < 4; r++) {
            int idx = tid + r * 256;
            int row = idx >> 3, c = idx & 7;
            const float4* s = (const float4*)(x + (size_t)(mbase + row) * 512 + k0 + c * 8);
            pa[r][0] = s[0];
            pa[r][1] = s[1];
        }
    };
    auto storeA = [&](int buf) {
        #pragma unroll
        for (int r = 0; r < 4; r++) {
            int idx = tid + r * 256;
            int row = idx >> 3, c = idx & 7;
            __half2 h0 = __halves2half2(__float2half_rn(pa[r][0].x), __float2half_rn(pa[r][0].y));
            __half2 h1 = __halves2half2(__float2half_rn(pa[r][0].z), __float2half_rn(pa[r][0].w));
            __half2 h2 = __halves2half2(__float2half_rn(pa[r][1].x), __float2half_rn(pa[r][1].y));
            __half2 h3 = __halves2half2(__float2half_rn(pa[r][1].z), __float2half_rn(pa[r][1].w));
            uint4 v = make_uint4(*(uint32_t*)&h0, *(uint32_t*)&h1, *(uint32_t*)&h2, *(uint32_t*)&h3);
            *(uint4*)(k1sm + (K1_BS_BYTES + buf * 16384u) + row * 128 + (((c ^ (row & 7)) & 7) << 4)) = v;
        }
    };

    float acc[4][4];
    #pragma unroll
    for (int j = 0; j < 4; j++)
        #pragma unroll
        for (int q = 0; q < 4; q++) acc[j][q] = 0.f;

    loadA(0);
    storeA(0);
    loadA(1);
    __syncthreads();

    for (int ch = 0; ch < 8; ch++) {
        const int buf = ch & 1;
        if (ch < 7) {
            storeA(1 - buf);
            if (ch < 6) loadA(ch + 2);
        }
        const uint32_t ab = ah_base + (uint32_t)buf * 16384u;
        #pragma unroll
        for (int kk = 0; kk < 4; kk++) {
            const int cb = 2 * kk + (lane >> 4);
            uint32_t a0, a1, a2, a3;
            {
                int row = wm + (lane & 15);
                LDMATRIX_X4(a0, a1, a2, a3, ab + row * 128 + (((cb ^ (row & 7)) & 7) << 4));
            }
            uint32_t bfr[4][2];
            #pragma unroll
            for (int j = 0; j < 2; j++) {
                int row = j * 16 + (lane & 15);
                uint32_t r0, r1, r2, r3;
                LDMATRIX_X4(r0, r1, r2, r3,
                            bs_base + row * 1040 + ch * 128 + kk * 32 + ((lane >> 4) << 4));
                bfr[2*j][0] = r0;   bfr[2*j][1] = r2;
                bfr[2*j+1][0] = r1; bfr[2*j+1][1] = r3;
            }
            #pragma unroll
            for (int j = 0; j < 4; j++)
                MMA_FP16(acc[j][0], acc[j][1], acc[j][2], acc[j][3],
                         a0, a1, a2, a3, bfr[j][0], bfr[j][1]);
        }
        __syncthreads();
    }

    const int r0 = mbase + wm + (lane >> 2);
    #pragma unroll
    for (int j = 0; j < 4; j++) {
        const int col = j * 8 + (lane & 3) * 2;
        const float bb0 = (col < 16) ? b0[col]     : b1[col - 16];
        const float bb1 = (col + 1 < 16) ? b0[col + 1] : b1[col + 1 - 16];
        __half2 o0 = __halves2half2(__float2half_rn(acc[j][0] + bb0),
                                    __float2half_rn(acc[j][1] + bb1));
        __half2 o1 = __halves2half2(__float2half_rn(acc[j][2] + bb0),
                                    __float2half_rn(acc[j][3] + bb1));
        *(__half2*)(g_t + (size_t)r0 * 32 + col)       = o0;
        *(__half2*)(g_t + (size_t)(r0 + 8) * 32 + col) = o1;
    }
}

// ====================================================================
// K2: windowed mixing, 256 threads = 2 window-groups, 8 windows/thread
// (4 passes of 16 windows/block). Inner: 2 LDS.128 + 8 FFMA per d.
// ====================================================================
__global__ __launch_bounds__(256) void k2_mix(
    const float* __restrict__ fw0, const float* __restrict__ fb0,
    const float* __restrict__ fw1, const float* __restrict__ fb1)
{
    extern __shared__ float sm[];
    float (*Wsm)[129] = (float (*)[129])sm;
    __shared__ float vst[2][128][8];

    const int mix  = blockIdx.x >> 7;
    const int head = (blockIdx.x >> 4) & 7;
    const int wt   = blockIdx.x & 15;
    const float* fw = mix ? fw1 : fw0;
    const float* fb = mix ? fb1 : fb0;
    const int tt = threadIdx.x;
    const int t   = tt & 127;
    const int grp = tt >> 7;

    for (int i = tt; i < 128 * 128; i += 256) {
        int d = i & 127;
        int f = i >> 7;
        Wsm[d][f] = fw[f * 1024 + head * 128 + d];
    }
    const int ch = mix * 16 + head * 2 + (t & 1);
    const float fbv = fb[t];
    __syncthreads();

    for (int pass = 0; pass < 4; pass++) {
        int px[8];
        #pragma unroll
        for (int j = 0; j < 8; j++) {
            int wg = wt * 64 + pass * 16 + grp * 8 + j;
            int Bb = wg >> 4, nw = wg & 15;
            int b = Bb >> 2, n1 = (Bb >> 1) & 1, n2 = Bb & 1;
            int row, col;
            if (mix == 0) { row = 2 * (t >> 2) + n1;          col = 4 * nw + 2 * ((t >> 1) & 1) + n2; }
            else          { row = 4 * nw + 2 * (t >> 6) + n1; col = 2 * ((t >> 1) & 31) + n2; }
            int pix = (b * 64 + row) * 64 + col;
            px[j] = pix;
            vst[grp][t][j] = __half2float(g_t[(size_t)pix * 32 + ch]);
        }
        __syncthreads();
        float a[8];
        #pragma unroll
        for (int j = 0; j < 8; j++) a[j] = fbv;
        #pragma unroll 4
        for (int d = 0; d < 128; d++) {
            float4 v0 = *(const float4*)&vst[grp][d][0];
            float4 v1 = *(const float4*)&vst[grp][d][4];
            float wv = Wsm[d][t];
            a[0] += v0.x * wv; a[1] += v0.y * wv; a[2] += v0.z * wv; a[3] += v0.w * wv;
            a[4] += v1.x * wv; a[5] += v1.y * wv; a[6] += v1.z * wv; a[7] += v1.w * wv;
        }
        #pragma unroll
        for (int j = 0; j < 8; j++)
            g_mixed[(size_t)px[j] * 32 + ch] = a[j];
        __syncthreads();
    }
}

// ====================================================================
// K3: MixC -> fp16 A plane + partial sums; x-loads software-pipelined.
// ====================================================================
__global__ __launch_bounds__(256) void k3_mixc(
    const float* __restrict__ x,
    const float* __restrict__ cwg, const float* __restrict__ cbg)
{
    const int bx = blockIdx.x;
    const int b = bx >> 7;
    const int rem = bx & 127;
    const int tile = rem >> 1;
    const int chH = rem & 1;
    const int ty = tile >> 3, tx = tile & 7;
    const int ch = chH * 256 + threadIdx.x;

    float cwr[16], cbr[4];
    #pragma unroll
    for (int i = 0; i < 16; i++) cwr[i] = cwg[ch*16 + i];
    #pragma unroll
    for (int p = 0; p < 4; p++) cbr[p] = cbg[ch*4 + p];

    auto xload = [&](int bi, float* x4) {
        int brow = bi >> 2, bcol = bi & 3;
        int r0 = ty*8 + brow*2, c0 = tx*8 + bcol*2;
        #pragma unroll
        for (int q = 0; q < 4; q++) {
            int q1 = q >> 1, q2 = q & 1;
            x4[q] = x[(size_t)((b*64 + r0 + q1) * 64 + c0 + q2) * 512 + ch];
        }
    };

    float ssum = 0.f;
    float xc[4], xn[4];
    xload(0, xc);
    for (int bi = 0; bi < 16; bi++) {
        if (bi < 15) xload(bi + 1, xn);
        int brow = bi >> 2, bcol = bi & 3;
        int r0 = ty*8 + brow*2, c0 = tx*8 + bcol*2;
        #pragma unroll
        for (int p = 0; p < 4; p++) {
            int p1 = p >> 1, p2 = p & 1;
            float cv = cbr[p];
            #pragma unroll
            for (int q = 0; q < 4; q++) cv += xc[q] * cwr[q*4 + p];
            const size_t pix = (size_t)((b*64 + r0 + p1) * 64 + c0 + p2);
            g_Ahi[pix * AK + ch] = __float2half_rn(cv);
            ssum += cv;
        }
        #pragma unroll
        for (int q = 0; q < 4; q++) xc[q] = xn[q];
    }
    g_part[(size_t)(b*64 + tile) * 512 + ch] = ssum;
}

// ====================================================================
// K2m: per-(batch, 512-pixel slab) sums of g_mixed -> g_mmean2.
// ====================================================================
__global__ __launch_bounds__(256) void k2m_mean()
{
    __shared__ float red[8][32];
    const int b = blockIdx.x, gg = blockIdx.y;
    const int t = threadIdx.x;
    const int cc = t & 31, sub = t >> 5;
    float s = 0.f;
    const float* src = g_mixed + ((size_t)(b * 4096 + gg * 512 + sub * 64)) * 32 + cc;
    #pragma unroll 8
    for (int i = 0; i < 64; i++) s += src[(size_t)i * 32];
    red[sub][cc] = s;
    __syncthreads();
    if (t < 32) {
        float tot = 0.f;
        #pragma unroll
        for (int g2 = 0; g2 < 8; g2++) tot += red[g2][t];
        g_mmean2[(b * 8 + gg) * 32 + t] = tot;
    }
}

// ====================================================================
// K4 fused: mean -> fc1+gelu (4x parallel) -> fc2 -> softmax.
// ====================================================================
__global__ __launch_bounds__(512) void k4_fused(
    const float* __restrict__ fc1w, const float* __restrict__ fc1b,
    const float* __restrict__ fc2w, const float* __restrict__ fc2b,
    const float* __restrict__ P0,   const float* __restrict__ pb0,
    const float* __restrict__ P1,   const float* __restrict__ pb1)
{
    __shared__ float asm_[512];
    __shared__ float hsm[128];
    __shared__ float fsm[1536];
    __shared__ float mm[32];
    const int b = blockIdx.x, t = threadIdx.x;

    if (t < 32) {
        float tot = 0.f;
        #pragma unroll
        for (int gg = 0; gg < 8; gg++) tot += g_mmean2[(b * 8 + gg) * 32 + t];
        mm[t] = tot;
    }
    __syncthreads();

    float s = 0.f;
    #pragma unroll 8
    for (int tl = 0; tl < 64; tl++) s += g_part[(size_t)(b*64 + tl) * 512 + t];
    float hw = 0.f;
    #pragma unroll
    for (int i = 0; i < 16; i++) {
        hw += mm[i]      * P0[i*512 + t];
        hw += mm[16 + i] * P1[i*512 + t];
    }
    asm_[t] = (s + hw) * (1.0f / 4096.0f) + pb0[t] + pb1[t];
    __syncthreads();

    {
        const int n = t >> 2, l4 = t & 3;
        const int k0 = l4 * 128;
        float acc = 0.f;
        #pragma unroll 8
        for (int k = 0; k < 128; k++) acc += asm_[k0 + k] * fc1w[(k0 + k) * 128 + n];
        acc += __shfl_xor_sync(0xffffffffu, acc, 1, 4);
        acc += __shfl_xor_sync(0xffffffffu, acc, 2, 4);
        if (l4 == 0) {
            acc += fc1b[n];
            hsm[n] = 0.5f * acc * (1.0f + erff(acc * 0.70710678118654752f));
        }
    }
    __syncthreads();

    #pragma unroll
    for (int r = 0; r < 3; r++) {
        int n = t + r * 512;
        float acc = fc2b[n];
        #pragma unroll 8
        for (int j = 0; j < 128; j++) acc += hsm[j] * fc2w[j*1536 + n];
        fsm[n] = acc;
    }
    __syncthreads();

    float v0 = fsm[t*3], v1 = fsm[t*3+1], v2 = fsm[t*3+2];
    float mx = fmaxf(v0, fmaxf(v1, v2));
    float e0 = expf(v0-mx), e1 = expf(v1-mx), e2 = expf(v2-mx);
    float inv = 1.0f / (e0 + e1 + e2);
    g_a3[(0*16 + b)*512 + t] = e0 * inv;
    g_a3[(1*16 + b)*512 + t] = e1 * inv;
    g_a3[(2*16 + b)*512 + t] = e2 * inv;
}

// ====================================================================
// K5w2: per-batch B cols 0..511: Bmat[b][n][k] = fp16(a2_b[k] * WtT[n][k]).
// ====================================================================
__global__ __launch_bounds__(256) void k5w2_scale()
{
    __shared__ float a2s[512];
    const int b = blockIdx.x;
    const int t = threadIdx.x;
    const int n = blockIdx.y * 8 + (t >> 5);
    const int kb = (t & 31) * 16;

    for (int k = t; k < 512; k += 256) a2s[k] = g_a3[(size_t)(32 + b)*512 + k];
    __syncthreads();

    const float* src = g_WtT + (size_t)n * 512 + kb;
    __half* dst = g_Bmat + ((size_t)b * 512 + n) * AK + kb;
    #pragma unroll
    for (int q = 0; q < 4; q++) {
        float4 w = *(const float4*)(src + q * 4);
        __half h0 = __float2half_rn(w.x * a2s[kb + q*4 + 0]);
        __half h1 = __float2half_rn(w.y * a2s[kb + q*4 + 1]);
        __half h2 = __float2half_rn(w.z * a2s[kb + q*4 + 2]);
        __half h3 = __float2half_rn(w.w * a2s[kb + q*4 + 3]);
        __half2 p0 = __halves2half2(h0, h1), p1 = __halves2half2(h2, h3);
        *(uint2*)(dst + q * 4) = make_uint2(*(uint32_t*)&p0, *(uint32_t*)&p1);
    }
}

// ====================================================================
// K6: per-batch reduced weights Q_b (32x512) -> Bmat cols 512..543 (fp16)
// + zero-pad cols 544..575, plus fused bias.
// ====================================================================
__global__ __launch_bounds__(256) void k6_prep(
    const float* __restrict__ P0, const float* __restrict__ pb0,
    const float* __restrict__ P1, const float* __restrict__ pb1,
    const float* __restrict__ P,  const float* __restrict__ pb)
{
    extern __shared__ float k6sm[];
    const int b = blockIdx.x, t = threadIdx.x;
    const int ig = t >> 6;
    const int nn = t & 63;
    const int n = blockIdx.y * 64 + nn;
    const float* a0 = g_a3 + (size_t)b * 512;
    const float* a1 = g_a3 + (size_t)(16 + b) * 512;

    for (int e = t; e < 8192; e += 256) {
        int ch = e & 511;
        k6sm[e]        = P0[e] * a0[ch];
        k6sm[8192 + e] = P1[e] * a1[ch];
    }
    for (int ch = t; ch < 512; ch += 256)
        k6sm[16384 + ch] = pb0[ch]*a0[ch] + pb1[ch]*a1[ch];
    __syncthreads();

    const float* sPa = k6sm + (ig >= 2 ? 8192 : 0) + ((ig & 1) * 8) * 512;

    float acc8[8];
    #pragma unroll
    for (int j = 0; j < 8; j++) acc8[j] = 0.f;
    float bias = 0.f;

    for (int ch = 0; ch < 512; ch += 4) {
        float p0 = P[(size_t)(ch+0)*512 + n];
        float p1 = P[(size_t)(ch+1)*512 + n];
        float p2 = P[(size_t)(ch+2)*512 + n];
        float p3 = P[(size_t)(ch+3)*512 + n];
        if (ig == 0) {
            float4 sv = *(const float4*)&k6sm[16384 + ch];
            bias += sv.x*p0 + sv.y*p1 + sv.z*p2 + sv.w*p3;
        }
        #pragma unroll
        for (int j = 0; j < 8; j++) {
            float4 v = *(const float4*)&sPa[j*512 + ch];
            acc8[j] += v.x*p0 + v.y*p1 + v.z*p2 + v.w*p3;
        }
    }

    if (ig == 0) g_bias[(size_t)b*512 + n] = pb[n] + bias;
    __half* q = g_Bmat + ((size_t)b*512 + n) * AK + 512 + ig * 8;
    #pragma unroll
    for (int j = 0; j < 8; j++) q[j] = __float2half_rn(acc8[j]);
    *(uint4*)(g_Bmat + ((size_t)b*512 + n) * AK + 544 + ig * 8) = make_uint4(0,0,0,0);
}

// ====================================================================
// K5a-mini: g_mixed fp32 -> fp16 into A cols 512..543 + zero cols 544..575.
// ====================================================================
__global__ __launch_bounds__(256) void k5a_mix()
{
    const int gid = blockIdx.x * 256 + threadIdx.x;
    const int p  = gid >> 3;
    const int kq = (gid & 7) << 2;
    float4 m = *(const float4*)(g_mixed + (size_t)p * 32 + kq);
    __half2 h0 = __halves2half2(__float2half_rn(m.x), __float2half_rn(m.y));
    __half2 h1 = __halves2half2(__float2half_rn(m.z), __float2half_rn(m.w));
    *(uint2*)(g_Ahi + (size_t)p * AK + 512 + kq) = make_uint2(*(uint32_t*)&h0, *(uint32_t*)&h1);
    *(uint2*)(g_Ahi + (size_t)p * AK + 544 + kq) = make_uint2(0u, 0u);
}

// ====================================================================
// K5b: fp16 single-pass HMMA GEMM, 2 CTAs/SM (unchanged from best).
// ====================================================================
#define K5B_STG 32768u

__global__ __launch_bounds__(256, 2) void k5b_gemm(float* __restrict__ out)
{
    extern __shared__ char dsm[];
    const uint32_t base = smem_u32(dsm);

    const int tid  = threadIdx.x;
    const int wid  = tid >> 5;
    const int lane = tid & 31;
    const int nbase = blockIdx.x * 128;
    const int mbase = blockIdx.y * 128;
    const int b = mbase >> 12;
    const int wm = (wid >> 2) * 64;
    const int wn = (wid & 3) * 32;

    float acc[4][4][4];
    #pragma unroll
    for (int i = 0; i < 4; i++)
        #pragma unroll
        for (int j = 0; j < 4; j++)
            #pragma unroll
            for (int q = 0; q < 4; q++) acc[i][j][q] = 0.f;

    auto fill = [&](int s, int ch) {
        const uint32_t st = base + (uint32_t)s * K5B_STG;
        const int k0 = ch * 64;
        #pragma unroll
        for (int r = 0; r < 4; r++) {
            int idx = tid + r * 256;
            int row = idx >> 3, c = idx & 7;
            uint32_t dst = st + row * 128 + (((c ^ (row & 7)) & 7) << 4);
            CP_ASYNC16(dst, g_Ahi + (size_t)(mbase + row) * AK + k0 + c * 8);
        }
        #pragma unroll
        for (int r = 0; r < 4; r++) {
            int idx = tid + r * 256;
            int row = idx >> 3, c = idx & 7;
            uint32_t dst = st + 16384u + row * 128 + (((c ^ (row & 7)) & 7) << 4);
            CP_ASYNC16(dst, g_Bmat + ((size_t)b * 512 + nbase + row) * AK + k0 + c * 8);
        }
        CP_COMMIT();
    };

    fill(0, 0);
    fill(1, 1);

    for (int ch = 0; ch < 9; ch++) {
        const int s = ch % 3;
        const uint32_t st = base + (uint32_t)s * K5B_STG;
        if (ch == 8) { CP_WAIT0(); } else { CP_WAIT1(); }
        __syncthreads();
        if (ch + 2 <= 8) fill((ch + 2) % 3, ch + 2);

        #pragma unroll
        for (int kk = 0; kk < 4; kk++) {
            const int cb = 2 * kk + (lane >> 4);
            uint32_t bfr[4][2];
            #pragma unroll
            for (int j = 0; j < 2; j++) {
                int row = wn + j * 16 + (lane & 15);
                uint32_t r0, r1, r2, r3;
                LDMATRIX_X4(r0, r1, r2, r3,
                            st + 16384u + row * 128 + (((cb ^ (row & 7)) & 7) << 4));
                bfr[2*j][0] = r0;   bfr[2*j][1] = r2;
                bfr[2*j+1][0] = r1; bfr[2*j+1][1] = r3;
            }
            uint32_t a[4][4];
            #pragma unroll
            for (int i = 0; i < 4; i++) {
                int row = wm + i * 16 + (lane & 15);
                LDMATRIX_X4(a[i][0], a[i][1], a[i][2], a[i][3],
                            st + row * 128 + (((cb ^ (row & 7)) & 7) << 4));
            }
            #pragma unroll
            for (int i = 0; i < 4; i++)
                #pragma unroll
                for (int j = 0; j < 4; j++)
                    MMA_FP16(acc[i][j][0], acc[i][j][1], acc[i][j][2], acc[i][j][3],
                             a[i][0], a[i][1], a[i][2], a[i][3], bfr[j][0], bfr[j][1]);
        }
    }

    const float* bias = g_bias + (size_t)b * 512;
    #pragma unroll
    for (int i = 0; i < 4; i++) {
        const int r0 = mbase + wm + i * 16 + (lane >> 2);
        #pragma unroll
        for (int j = 0; j < 4; j++) {
            const int col = nbase + wn + j * 8 + (lane & 3) * 2;
            const float2 bb = *(const float2*)(bias + col);
            float2 o0 = make_float2(acc[i][j][0] + bb.x, acc[i][j][1] + bb.y);
            float2 o1 = make_float2(acc[i][j][2] + bb.x, acc[i][j][3] + bb.y);
            *(float2*)(out + (size_t)r0 * 512 + col)       = o0;
            *(float2*)(out + (size_t)(r0 + 8) * 512 + col) = o1;
        }
    }
}

// ====================================================================
extern "C" void kernel_launch(void* const* d_in, const int* in_sizes, int n_in,
                              void* d_out, int out_size)
{
    (void)in_sizes; (void)n_in; (void)out_size;
    const float* x       = (const float*)d_in[0];
    const float* mh_pinw = (const float*)d_in[1];
    const float* mh_pinb = (const float*)d_in[2];
    const float* mh_fw   = (const float*)d_in[3];
    const float* mh_fb   = (const float*)d_in[4];
    const float* mh_pow  = (const float*)d_in[5];
    const float* mh_pob  = (const float*)d_in[6];
    const float* mw_pinw = (const float*)d_in[7];
    const float* mw_pinb = (const float*)d_in[8];
    const float* mw_fw   = (const float*)d_in[9];
    const float* mw_fb   = (const float*)d_in[10];
    const float* mw_pow  = (const float*)d_in[11];
    const float* mw_pob  = (const float*)d_in[12];
    const float* c_w     = (const float*)d_in[13];
    const float* c_b     = (const float*)d_in[14];
    const float* fc1w    = (const float*)d_in[15];
    const float* fc1b    = (const float*)d_in[16];
    const float* fc2w    = (const float*)d_in[17];
    const float* fc2b    = (const float*)d_in[18];
    const float* projw   = (const float*)d_in[19];
    const float* projb   = (const float*)d_in[20];
    float* out = (float*)d_out;

    const int k1_smem  = (int)K1_BS_BYTES + 2 * 16384;  // 66048 B
    const int k2_smem  = 128 * 129 * sizeof(float);     // 66048 B
    const int k6_smem  = (16384 + 512) * 4;             // 67584 B
    const int k5b_smem = 3 * (int)K5B_STG;              // 98304 B
    cudaFuncSetAttribute(k1_proj_in, cudaFuncAttributeMaxDynamicSharedMemorySize, k1_smem);
    cudaFuncSetAttribute(k2_mix,     cudaFuncAttributeMaxDynamicSharedMemorySize, k2_smem);
    cudaFuncSetAttribute(k6_prep,    cudaFuncAttributeMaxDynamicSharedMemorySize, k6_smem);
    cudaFuncSetAttribute(k5b_gemm,   cudaFuncAttributeMaxDynamicSharedMemorySize, k5b_smem);

    k3_mixc<<<2048, 256>>>(x, c_w, c_b);
    k5w1_transpose<<<dim3(16, 16), 256>>>(projw);
    k1_proj_in<<<512, 256, k1_smem>>>(x, mh_pinw, mh_pinb, mw_pinw, mw_pinb);
    k2_mix<<<256, 256, k2_smem>>>(mh_fw, mh_fb, mw_fw, mw_fb);
    k2m_mean<<<dim3(16, 8), 256>>>();
    k4_fused<<<16, 512>>>(fc1w, fc1b, fc2w, fc2b, mh_pow, mh_pob, mw_pow, mw_pob);
    k5w2_scale<<<dim3(16, 64), 256>>>();
    k6_prep<<<dim3(16, 8), 256, k6_smem>>>(mh_pow, mh_pob, mw_pow, mw_pob, projw, projb);
    k5a_mix<<<2048, 256>>>();
    k5b_gemm<<<dim3(4, 512), 256, k5b_smem>>>(out);
}